// round 15
// baseline (speedup 1.0000x reference)
#include <cuda_runtime.h>
#include <cstdint>

// ----------------------------------------------------------------------------
// TuckerLinear on GB300 (sm_103a) — 3-kernel pipeline, f32x2 packed token pairs
//   k_input : gather(x, perm) + 3 input-mode contractions  -> g_Y2
//   k_gemm  : Z = Y @ core(512x512)^T                      -> g_Z2
//   k_output: 3 output-mode contractions + inv-perm + scale/bias -> out
// ----------------------------------------------------------------------------

typedef unsigned long long ull_t;

__device__ __forceinline__ ull_t dup_f32x2(float v) {
    ull_t r; unsigned int b = __float_as_uint(v);
    asm("mov.b64 %0, {%1, %1};" : "=l"(r) : "r"(b));
    return r;
}
__device__ __forceinline__ ull_t pack_f32x2(float a, float b) {
    ull_t r;
    asm("mov.b64 %0, {%1, %2};" : "=l"(r)
        : "r"(__float_as_uint(a)), "r"(__float_as_uint(b)));
    return r;
}
__device__ __forceinline__ float2 unpack_f32x2(ull_t v) {
    unsigned int lo, hi;
    asm("mov.b64 {%0, %1}, %2;" : "=r"(lo), "=r"(hi) : "l"(v));
    return make_float2(__uint_as_float(lo), __uint_as_float(hi));
}
__device__ __forceinline__ ull_t fma_f32x2(ull_t a, ull_t b, ull_t c) {
    ull_t d;
    asm("fma.rn.f32x2 %0, %1, %2, %3;" : "=l"(d) : "l"(a), "l"(b), "l"(c));
    return d;
}

// Scratch (packed token pairs): 4096 pairs x 512 cols each.
__device__ ull_t g_Y2[4096 * 512];
__device__ ull_t g_Z2[4096 * 512];

// ============================================================================
// Kernel 1: gather + input-side contractions. One CTA = TWO token pairs,
// 256 threads. [R11-proven]
// ============================================================================
#define K1_SMEM_ULL (2*4096 + 2*8*257 + 3*128)
#define K1_SMEM_BYTES (K1_SMEM_ULL * 8)

__global__ void __launch_bounds__(256) k_input(
    const float* __restrict__ x, const int* __restrict__ iperm,
    const float* __restrict__ fi0, const float* __restrict__ fi1,
    const float* __restrict__ fi2)
{
    extern __shared__ __align__(16) char smem_raw[];
    ull_t* xs2a = (ull_t*)smem_raw;          // [4096] pair A (t2a aliases head)
    ull_t* xs2b = xs2a + 4096;               // [4096] pair B
    ull_t* t2a  = xs2a;
    ull_t* t2b  = xs2b;
    ull_t* t1a  = xs2b + 4096;               // [8*257]
    ull_t* t1b  = t1a + 8*257;
    ull_t* fi0d = t1b + 8*257;
    ull_t* fi1d = fi0d + 128;
    ull_t* fi2d = fi1d + 128;

    const int tid = threadIdx.x;
    const int pair0 = blockIdx.x * 2;

    const float4* r0 = (const float4*)(x + (size_t)pair0 * 2 * 4096);
    const float4* r1 = r0 + 1024;
    const float4* r2 = r1 + 1024;
    const float4* r3 = r2 + 1024;
    for (int i = tid; i < 1024; i += 256) {
        float4 a = r0[i], b = r1[i], c = r2[i], d = r3[i];
        xs2a[4*i+0] = pack_f32x2(a.x, b.x); xs2a[4*i+1] = pack_f32x2(a.y, b.y);
        xs2a[4*i+2] = pack_f32x2(a.z, b.z); xs2a[4*i+3] = pack_f32x2(a.w, b.w);
        xs2b[4*i+0] = pack_f32x2(c.x, d.x); xs2b[4*i+1] = pack_f32x2(c.y, d.y);
        xs2b[4*i+2] = pack_f32x2(c.z, d.z); xs2b[4*i+3] = pack_f32x2(c.w, d.w);
    }
    if (tid < 128) {
        fi0d[tid] = dup_f32x2(fi0[tid]);
        fi1d[tid] = dup_f32x2(fi1[tid]);
        fi2d[tid] = dup_f32x2(fi2[tid]);
    }
    __syncthreads();

    // Stage A: contract F. thread = de; both pairs share indices + weights.
    {
        const int de = tid;
        const int4* ip4 = (const int4*)(iperm + de*16);
        ull_t accA[8], accB[8];
        #pragma unroll
        for (int f = 0; f < 8; f++) { accA[f] = 0ull; accB[f] = 0ull; }
        #pragma unroll
        for (int k = 0; k < 4; k++) {
            int4 p = ip4[k];
            ull_t ax = xs2a[p.x], ay = xs2a[p.y], az = xs2a[p.z], aw = xs2a[p.w];
            ull_t bx = xs2b[p.x], by = xs2b[p.y], bz = xs2b[p.z], bw = xs2b[p.w];
            #pragma unroll
            for (int f = 0; f < 8; f++) {
                ull_t w0 = fi2d[(4*k+0)*8 + f];
                accA[f] = fma_f32x2(ax, w0, accA[f]);
                accB[f] = fma_f32x2(bx, w0, accB[f]);
                ull_t w1 = fi2d[(4*k+1)*8 + f];
                accA[f] = fma_f32x2(ay, w1, accA[f]);
                accB[f] = fma_f32x2(by, w1, accB[f]);
                ull_t w2 = fi2d[(4*k+2)*8 + f];
                accA[f] = fma_f32x2(az, w2, accA[f]);
                accB[f] = fma_f32x2(bz, w2, accB[f]);
                ull_t w3 = fi2d[(4*k+3)*8 + f];
                accA[f] = fma_f32x2(aw, w3, accA[f]);
                accB[f] = fma_f32x2(bw, w3, accB[f]);
            }
        }
        #pragma unroll
        for (int f = 0; f < 8; f++) {
            t1a[f*257 + de] = accA[f];
            t1b[f*257 + de] = accB[f];
        }
    }
    __syncthreads();

    // Stage B (register-tiled): thread = (pair, D, f); computes ALL 8 e.
    {
        const int f_    = tid & 7;
        const int D_    = (tid >> 3) & 15;
        const int psel  = tid >> 7;
        ull_t* t1p = psel ? t1b : t1a;
        ull_t* t2p = psel ? t2b : t2a;

        const ull_t* src = &t1p[f_*257 + D_*16];
        ull_t tv[16];
        #pragma unroll
        for (int E = 0; E < 16; E++) tv[E] = src[E];   // scalar: odd stride

        ull_t acc[8];
        #pragma unroll
        for (int e = 0; e < 8; e++) acc[e] = 0ull;
        #pragma unroll
        for (int E = 0; E < 16; E++) {
            #pragma unroll
            for (int eh = 0; eh < 4; eh++) {
                ulonglong2 w = *(const ulonglong2*)&fi1d[E*8 + 2*eh];
                acc[2*eh]   = fma_f32x2(tv[E], w.x, acc[2*eh]);
                acc[2*eh+1] = fma_f32x2(tv[E], w.y, acc[2*eh+1]);
            }
        }
        __syncthreads();
        #pragma unroll
        for (int e = 0; e < 8; e++)
            t2p[D_*64 + e*8 + f_] = acc[e];
    }
    __syncthreads();

    // Stage C (register-tiled): thread = (pair, dh, ef); computes 4 d values.
    {
        const int ef    = tid & 63;
        const int dh    = (tid >> 6) & 1;
        const int psel  = tid >> 7;
        ull_t* t2p = psel ? t2b : t2a;
        ull_t* yout = &g_Y2[(size_t)(pair0 + psel) * 512];

        ull_t acc[4];
        #pragma unroll
        for (int j = 0; j < 4; j++) acc[j] = 0ull;
        #pragma unroll
        for (int D = 0; D < 16; D++) {
            ull_t zv = t2p[D*64 + ef];
            ulonglong2 w0 = *(const ulonglong2*)&fi0d[D*8 + dh*4];
            ulonglong2 w1 = *(const ulonglong2*)&fi0d[D*8 + dh*4 + 2];
            acc[0] = fma_f32x2(zv, w0.x, acc[0]);
            acc[1] = fma_f32x2(zv, w0.y, acc[1]);
            acc[2] = fma_f32x2(zv, w1.x, acc[2]);
            acc[3] = fma_f32x2(zv, w1.y, acc[3]);
        }
        #pragma unroll
        for (int j = 0; j < 4; j++)
            yout[(dh*4 + j)*64 + ef] = acc[j];
    }
}

// ============================================================================
// Kernel 2: core GEMM. CTA: 32 pairs x 128 o, 256 thr, 3 CTAs/SM (42KB smem,
// <=85 regs). Thread tile: 2 pairs x 8 o. Grid (128, 4) = 512 CTAs.
// ============================================================================
#define GP 32
#define GO 128
#define GK 16

__global__ void __launch_bounds__(256, 3) k_gemm(const float* __restrict__ core)
{
    __shared__ __align__(16) ull_t Ys[2][GK][GP + 2];   // 34 stride
    __shared__ __align__(16) ull_t Cs[2][GK][GO + 2];   // 130 stride

    const int tid = threadIdx.x;
    const int p0 = blockIdx.x * GP;
    const int o0 = blockIdx.y * GO;

    const int yrow = tid >> 3, yq = tid & 7;       // Y: 32 rows x 8 chunks(2ull)
    const int crow = tid >> 1, ch = tid & 1;       // C: 128 rows x 2 halves(8f)
    const int wid = tid >> 5, lane = tid & 31;
    const int pgrp = (lane & 7) + (wid & 1) * 8;   // 0..15 -> pairs pgrp*2..+1
    const int ogrp = (lane >> 3) + (wid >> 1) * 4; // 0..15 -> o ogrp*8..+7

    // prologue: chunk 0
    {
        ulonglong2 y0 = *(const ulonglong2*)&g_Y2[(size_t)(p0 + yrow)*512 + yq*2];
        Ys[0][yq*2+0][yrow] = y0.x;
        Ys[0][yq*2+1][yrow] = y0.y;
        const float4* cg = (const float4*)(core + (size_t)(o0 + crow)*512 + ch*8);
        float4 c0 = cg[0], c1 = cg[1];
        Cs[0][ch*8+0][crow] = dup_f32x2(c0.x); Cs[0][ch*8+1][crow] = dup_f32x2(c0.y);
        Cs[0][ch*8+2][crow] = dup_f32x2(c0.z); Cs[0][ch*8+3][crow] = dup_f32x2(c0.w);
        Cs[0][ch*8+4][crow] = dup_f32x2(c1.x); Cs[0][ch*8+5][crow] = dup_f32x2(c1.y);
        Cs[0][ch*8+6][crow] = dup_f32x2(c1.z); Cs[0][ch*8+7][crow] = dup_f32x2(c1.w);
    }
    __syncthreads();

    ull_t acc[2][8];
    #pragma unroll
    for (int i = 0; i < 2; i++)
        #pragma unroll
        for (int j = 0; j < 8; j++) acc[i][j] = 0ull;

    for (int kb = 0; kb < 32; kb++) {
        int b = kb & 1;
        ulonglong2 ny; float4 nc0, nc1;
        if (kb < 31) {
            ny = *(const ulonglong2*)&g_Y2[(size_t)(p0 + yrow)*512 + (kb+1)*GK + yq*2];
            const float4* cg = (const float4*)(core + (size_t)(o0 + crow)*512
                                               + (kb+1)*GK + ch*8);
            nc0 = cg[0]; nc1 = cg[1];
        }

        #pragma unroll
        for (int hh = 0; hh < GK; hh++) {
            ulonglong2 yv = *(const ulonglong2*)&Ys[b][hh][pgrp*2];
            ulonglong2 c0 = *(const ulonglong2*)&Cs[b][hh][ogrp*8];
            ulonglong2 c1 = *(const ulonglong2*)&Cs[b][hh][ogrp*8 + 2];
            ulonglong2 c2 = *(const ulonglong2*)&Cs[b][hh][ogrp*8 + 4];
            ulonglong2 c3 = *(const ulonglong2*)&Cs[b][hh][ogrp*8 + 6];
            ull_t c[8] = {c0.x, c0.y, c1.x, c1.y, c2.x, c2.y, c3.x, c3.y};
            #pragma unroll
            for (int j = 0; j < 8; j++) {
                acc[0][j] = fma_f32x2(yv.x, c[j], acc[0][j]);
                acc[1][j] = fma_f32x2(yv.y, c[j], acc[1][j]);
            }
        }

        if (kb < 31) {
            int nb = b ^ 1;
            Ys[nb][yq*2+0][yrow] = ny.x;
            Ys[nb][yq*2+1][yrow] = ny.y;
            Cs[nb][ch*8+0][crow] = dup_f32x2(nc0.x);
            Cs[nb][ch*8+1][crow] = dup_f32x2(nc0.y);
            Cs[nb][ch*8+2][crow] = dup_f32x2(nc0.z);
            Cs[nb][ch*8+3][crow] = dup_f32x2(nc0.w);
            Cs[nb][ch*8+4][crow] = dup_f32x2(nc1.x);
            Cs[nb][ch*8+5][crow] = dup_f32x2(nc1.y);
            Cs[nb][ch*8+6][crow] = dup_f32x2(nc1.z);
            Cs[nb][ch*8+7][crow] = dup_f32x2(nc1.w);
        }
        __syncthreads();
    }

    #pragma unroll
    for (int i = 0; i < 2; i++) {
        ull_t* zg = &g_Z2[(size_t)(p0 + pgrp*2 + i) * 512 + o0 + ogrp*8];
        ulonglong2 v;
        v.x = acc[i][0]; v.y = acc[i][1]; *(ulonglong2*)(zg)     = v;
        v.x = acc[i][2]; v.y = acc[i][3]; *(ulonglong2*)(zg + 2) = v;
        v.x = acc[i][4]; v.y = acc[i][5]; *(ulonglong2*)(zg + 4) = v;
        v.x = acc[i][6]; v.y = acc[i][7]; *(ulonglong2*)(zg + 6) = v;
    }
}

// ============================================================================
// Kernel 3: output expansion. One CTA = one pair. [R11-proven]
// ============================================================================
#define K3_SMEM_ULL (512 + 64*17 + 2048 + 16*257 + 3*128)
#define K3_SMEM_BYTES (K3_SMEM_ULL * 8)

__global__ void __launch_bounds__(256) k_output(
    const float* __restrict__ fo0, const float* __restrict__ fo1,
    const float* __restrict__ fo2,
    const float* __restrict__ bias, const float* __restrict__ alpha,
    const float* __restrict__ pds, const int* __restrict__ oinv,
    float* __restrict__ out)
{
    extern __shared__ __align__(16) char smem3[];
    ull_t* Zs   = (ull_t*)smem3;          // [512]  [a*64+b*8+c]
    ull_t* e1   = Zs + 512;               // [64*17]  [(a*8+b)*17 + C]
    ull_t* e2   = e1 + 64*17;             // [2048]   [a*256 + B*16 + C]
    ull_t* arr  = e2 + 2048;              // [16*257] [A*257 + bc]
    ull_t* fo0t = arr + 16*257;           // [a*16+A]
    ull_t* fo1t = fo0t + 128;             // [b*16+B]
    ull_t* fo2t = fo1t + 128;             // [c*16+C]

    const int tid = threadIdx.x;
    const int pair = blockIdx.x;
    const float alphaV = __ldg(alpha);

    const ull_t* zsrc = &g_Z2[(size_t)pair * 512];
    #pragma unroll
    for (int k = 0; k < 2; k++) Zs[tid + k*256] = zsrc[tid + k*256];
    if (tid < 128) {
        int M_ = tid >> 3, r_ = tid & 7;      // f[M,r] -> ft[r*16+M]
        fo0t[r_*16 + M_] = dup_f32x2(fo0[tid]);
        fo1t[r_*16 + M_] = dup_f32x2(fo1[tid]);
        fo2t[r_*16 + M_] = dup_f32x2(fo2[tid]);
    }
    __syncthreads();

    // Stage 1: contract c. Thread tile 2(ab) x 2(C).
    {
        int ab0 = (tid >> 3) * 2;
        int C0  = (tid & 7) * 2;
        ull_t a00 = 0, a01 = 0, a10 = 0, a11 = 0;
        #pragma unroll
        for (int c_ = 0; c_ < 8; c_++) {
            ull_t z0 = Zs[ab0*8 + c_];
            ull_t z1 = Zs[(ab0+1)*8 + c_];
            ulonglong2 w = *(const ulonglong2*)&fo2t[c_*16 + C0];
            a00 = fma_f32x2(z0, w.x, a00); a01 = fma_f32x2(z0, w.y, a01);
            a10 = fma_f32x2(z1, w.x, a10); a11 = fma_f32x2(z1, w.y, a11);
        }
        e1[ab0*17 + C0]       = a00;
        e1[ab0*17 + C0 + 1]   = a01;
        e1[(ab0+1)*17 + C0]   = a10;
        e1[(ab0+1)*17 + C0+1] = a11;
    }
    __syncthreads();

    // Stage 2: contract b. Thread tile 8(B), fixed (a, C).
    {
        int a_ = tid >> 5;
        int C_ = (tid >> 1) & 15;
        int B0 = (tid & 1) * 8;
        ull_t acc[8];
        #pragma unroll
        for (int j = 0; j < 8; j++) acc[j] = 0ull;
        #pragma unroll
        for (int b_ = 0; b_ < 8; b_++) {
            ull_t ev = e1[(a_*8 + b_)*17 + C_];
            #pragma unroll
            for (int j = 0; j < 4; j++) {
                ulonglong2 w = *(const ulonglong2*)&fo1t[b_*16 + B0 + 2*j];
                acc[2*j]   = fma_f32x2(ev, w.x, acc[2*j]);
                acc[2*j+1] = fma_f32x2(ev, w.y, acc[2*j+1]);
            }
        }
        #pragma unroll
        for (int j = 0; j < 8; j++)
            e2[a_*256 + (B0+j)*16 + C_] = acc[j];
    }
    __syncthreads();

    // Stage 3a: contract a (natural order). Thread tile 2(bc) x 8(A).
    {
        int bc0 = (tid >> 1) * 2;
        int A0  = (tid & 1) * 8;
        ull_t acc[2][8];
        #pragma unroll
        for (int i = 0; i < 2; i++)
            #pragma unroll
            for (int j = 0; j < 8; j++) acc[i][j] = 0ull;
        #pragma unroll
        for (int a_ = 0; a_ < 8; a_++) {
            ull_t z0 = e2[a_*256 + bc0];
            ull_t z1 = e2[a_*256 + bc0 + 1];
            #pragma unroll
            for (int j = 0; j < 4; j++) {
                ulonglong2 w = *(const ulonglong2*)&fo0t[a_*16 + A0 + 2*j];
                acc[0][2*j]   = fma_f32x2(z0, w.x, acc[0][2*j]);
                acc[0][2*j+1] = fma_f32x2(z0, w.y, acc[0][2*j+1]);
                acc[1][2*j]   = fma_f32x2(z1, w.x, acc[1][2*j]);
                acc[1][2*j+1] = fma_f32x2(z1, w.y, acc[1][2*j+1]);
            }
        }
        #pragma unroll
        for (int j = 0; j < 8; j++) {
            arr[(A0+j)*257 + bc0]     = acc[0][j];
            arr[(A0+j)*257 + bc0 + 1] = acc[1][j];
        }
    }
    __syncthreads();

    // Stage 3b: permuted read + scale/bias + coalesced store.
    float* o0p = out + (size_t)pair * 2 * 4096;
    float* o1p = o0p + 4096;
    #pragma unroll
    for (int k = 0; k < 16; k++) {
        int j = tid + k*256;
        int o = __ldg(oinv + j);
        float2 v = unpack_f32x2(arr[o + (o >> 8)]);
        float s = __ldg(pds + j) * alphaV, bb = __ldg(bias + j);
        o0p[j] = v.x * s + bb;
        o1p[j] = v.y * s + bb;
    }
}

// ============================================================================
// Launch
// ============================================================================
extern "C" void kernel_launch(void* const* d_in, const int* in_sizes, int n_in,
                              void* d_out, int out_size)
{
    const float* x     = (const float*)d_in[0];
    const float* core  = (const float*)d_in[1];
    const float* fo0   = (const float*)d_in[2];
    const float* fo1   = (const float*)d_in[3];
    const float* fo2   = (const float*)d_in[4];
    const float* fi0   = (const float*)d_in[5];
    const float* fi1   = (const float*)d_in[6];
    const float* fi2   = (const float*)d_in[7];
    const float* bias  = (const float*)d_in[8];
    const float* alpha = (const float*)d_in[9];
    const float* pds   = (const float*)d_in[10];
    const int*   iperm = (const int*)d_in[11];
    const int*   oinv  = (const int*)d_in[12];
    float* out = (float*)d_out;

    int NT = in_sizes[0] / 4096;      // tokens (8192)
    int nPairs = NT / 2;              // 4096

    cudaFuncSetAttribute(k_input, cudaFuncAttributeMaxDynamicSharedMemorySize,
                         K1_SMEM_BYTES);
    cudaFuncSetAttribute(k_output, cudaFuncAttributeMaxDynamicSharedMemorySize,
                         K3_SMEM_BYTES);

    k_input<<<nPairs/2, 256, K1_SMEM_BYTES>>>(x, iperm, fi0, fi1, fi2);
    dim3 ggrid(nPairs / GP, 512 / GO);
    k_gemm<<<ggrid, 256>>>(core);
    k_output<<<nPairs, 256, K3_SMEM_BYTES>>>(fo0, fo1, fo2, bias, alpha, pds,
                                             oinv, out);
}

// round 17
// speedup vs baseline: 1.0464x; 1.0464x over previous
#include <cuda_runtime.h>
#include <cstdint>

// ----------------------------------------------------------------------------
// TuckerLinear on GB300 (sm_103a) — 3-kernel pipeline, f32x2 packed token pairs
//   k_input : gather(x, perm) + 3 input-mode contractions  -> g_Y2
//   k_gemm  : Z = Y @ core(512x512)^T                      -> g_Z2
//   k_output: 3 output-mode contractions + inv-perm + scale/bias -> out
// NOTE: tcgen05 is unusable here — harness ptxas targets plain sm_103.
// ----------------------------------------------------------------------------

typedef unsigned long long ull_t;

__device__ __forceinline__ ull_t dup_f32x2(float v) {
    ull_t r; unsigned int b = __float_as_uint(v);
    asm("mov.b64 %0, {%1, %1};" : "=l"(r) : "r"(b));
    return r;
}
__device__ __forceinline__ ull_t pack_f32x2(float a, float b) {
    ull_t r;
    asm("mov.b64 %0, {%1, %2};" : "=l"(r)
        : "r"(__float_as_uint(a)), "r"(__float_as_uint(b)));
    return r;
}
__device__ __forceinline__ float2 unpack_f32x2(ull_t v) {
    unsigned int lo, hi;
    asm("mov.b64 {%0, %1}, %2;" : "=r"(lo), "=r"(hi) : "l"(v));
    return make_float2(__uint_as_float(lo), __uint_as_float(hi));
}
__device__ __forceinline__ ull_t fma_f32x2(ull_t a, ull_t b, ull_t c) {
    ull_t d;
    asm("fma.rn.f32x2 %0, %1, %2, %3;" : "=l"(d) : "l"(a), "l"(b), "l"(c));
    return d;
}

// Scratch (packed token pairs): 4096 pairs x 512 cols each.
__device__ ull_t g_Y2[4096 * 512];
__device__ ull_t g_Z2[4096 * 512];

// ============================================================================
// Kernel 1: gather + input-side contractions. One CTA = TWO token pairs,
// 256 threads. [R11-proven]
// ============================================================================
#define K1_SMEM_ULL (2*4096 + 2*8*257 + 3*128)
#define K1_SMEM_BYTES (K1_SMEM_ULL * 8)

__global__ void __launch_bounds__(256) k_input(
    const float* __restrict__ x, const int* __restrict__ iperm,
    const float* __restrict__ fi0, const float* __restrict__ fi1,
    const float* __restrict__ fi2)
{
    extern __shared__ __align__(16) char smem_raw[];
    ull_t* xs2a = (ull_t*)smem_raw;          // [4096] pair A (t2a aliases head)
    ull_t* xs2b = xs2a + 4096;               // [4096] pair B
    ull_t* t2a  = xs2a;
    ull_t* t2b  = xs2b;
    ull_t* t1a  = xs2b + 4096;               // [8*257]
    ull_t* t1b  = t1a + 8*257;
    ull_t* fi0d = t1b + 8*257;
    ull_t* fi1d = fi0d + 128;
    ull_t* fi2d = fi1d + 128;

    const int tid = threadIdx.x;
    const int pair0 = blockIdx.x * 2;

    const float4* r0 = (const float4*)(x + (size_t)pair0 * 2 * 4096);
    const float4* r1 = r0 + 1024;
    const float4* r2 = r1 + 1024;
    const float4* r3 = r2 + 1024;
    for (int i = tid; i < 1024; i += 256) {
        float4 a = r0[i], b = r1[i], c = r2[i], d = r3[i];
        xs2a[4*i+0] = pack_f32x2(a.x, b.x); xs2a[4*i+1] = pack_f32x2(a.y, b.y);
        xs2a[4*i+2] = pack_f32x2(a.z, b.z); xs2a[4*i+3] = pack_f32x2(a.w, b.w);
        xs2b[4*i+0] = pack_f32x2(c.x, d.x); xs2b[4*i+1] = pack_f32x2(c.y, d.y);
        xs2b[4*i+2] = pack_f32x2(c.z, d.z); xs2b[4*i+3] = pack_f32x2(c.w, d.w);
    }
    if (tid < 128) {
        fi0d[tid] = dup_f32x2(fi0[tid]);
        fi1d[tid] = dup_f32x2(fi1[tid]);
        fi2d[tid] = dup_f32x2(fi2[tid]);
    }
    __syncthreads();

    // Stage A: contract F. thread = de; both pairs share indices + weights.
    {
        const int de = tid;
        const int4* ip4 = (const int4*)(iperm + de*16);
        ull_t accA[8], accB[8];
        #pragma unroll
        for (int f = 0; f < 8; f++) { accA[f] = 0ull; accB[f] = 0ull; }
        #pragma unroll
        for (int k = 0; k < 4; k++) {
            int4 p = ip4[k];
            ull_t ax = xs2a[p.x], ay = xs2a[p.y], az = xs2a[p.z], aw = xs2a[p.w];
            ull_t bx = xs2b[p.x], by = xs2b[p.y], bz = xs2b[p.z], bw = xs2b[p.w];
            #pragma unroll
            for (int f = 0; f < 8; f++) {
                ull_t w0 = fi2d[(4*k+0)*8 + f];
                accA[f] = fma_f32x2(ax, w0, accA[f]);
                accB[f] = fma_f32x2(bx, w0, accB[f]);
                ull_t w1 = fi2d[(4*k+1)*8 + f];
                accA[f] = fma_f32x2(ay, w1, accA[f]);
                accB[f] = fma_f32x2(by, w1, accB[f]);
                ull_t w2 = fi2d[(4*k+2)*8 + f];
                accA[f] = fma_f32x2(az, w2, accA[f]);
                accB[f] = fma_f32x2(bz, w2, accB[f]);
                ull_t w3 = fi2d[(4*k+3)*8 + f];
                accA[f] = fma_f32x2(aw, w3, accA[f]);
                accB[f] = fma_f32x2(bw, w3, accB[f]);
            }
        }
        #pragma unroll
        for (int f = 0; f < 8; f++) {
            t1a[f*257 + de] = accA[f];
            t1b[f*257 + de] = accB[f];
        }
    }
    __syncthreads();

    // Stage B (register-tiled): thread = (pair, D, f); computes ALL 8 e.
    {
        const int f_    = tid & 7;
        const int D_    = (tid >> 3) & 15;
        const int psel  = tid >> 7;
        ull_t* t1p = psel ? t1b : t1a;
        ull_t* t2p = psel ? t2b : t2a;

        const ull_t* src = &t1p[f_*257 + D_*16];
        ull_t tv[16];
        #pragma unroll
        for (int E = 0; E < 16; E++) tv[E] = src[E];   // scalar: odd stride

        ull_t acc[8];
        #pragma unroll
        for (int e = 0; e < 8; e++) acc[e] = 0ull;
        #pragma unroll
        for (int E = 0; E < 16; E++) {
            #pragma unroll
            for (int eh = 0; eh < 4; eh++) {
                ulonglong2 w = *(const ulonglong2*)&fi1d[E*8 + 2*eh];
                acc[2*eh]   = fma_f32x2(tv[E], w.x, acc[2*eh]);
                acc[2*eh+1] = fma_f32x2(tv[E], w.y, acc[2*eh+1]);
            }
        }
        __syncthreads();
        #pragma unroll
        for (int e = 0; e < 8; e++)
            t2p[D_*64 + e*8 + f_] = acc[e];
    }
    __syncthreads();

    // Stage C (register-tiled): thread = (pair, dh, ef); computes 4 d values.
    {
        const int ef    = tid & 63;
        const int dh    = (tid >> 6) & 1;
        const int psel  = tid >> 7;
        ull_t* t2p = psel ? t2b : t2a;
        ull_t* yout = &g_Y2[(size_t)(pair0 + psel) * 512];

        ull_t acc[4];
        #pragma unroll
        for (int j = 0; j < 4; j++) acc[j] = 0ull;
        #pragma unroll
        for (int D = 0; D < 16; D++) {
            ull_t zv = t2p[D*64 + ef];
            ulonglong2 w0 = *(const ulonglong2*)&fi0d[D*8 + dh*4];
            ulonglong2 w1 = *(const ulonglong2*)&fi0d[D*8 + dh*4 + 2];
            acc[0] = fma_f32x2(zv, w0.x, acc[0]);
            acc[1] = fma_f32x2(zv, w0.y, acc[1]);
            acc[2] = fma_f32x2(zv, w1.x, acc[2]);
            acc[3] = fma_f32x2(zv, w1.y, acc[3]);
        }
        #pragma unroll
        for (int j = 0; j < 4; j++)
            yout[(dh*4 + j)*64 + ef] = acc[j];
    }
}

// ============================================================================
// Kernel 2: core GEMM. CTA: 64 pairs x 128 o, 256 thr, 2 CTAs/SM.
// Thread tile: 4 pairs x 8 o (64 acc regs). Grid (64, 4). [R11-proven]
// ============================================================================
#define GP 64
#define GO 128
#define GK 16

__global__ void __launch_bounds__(256, 2) k_gemm(const float* __restrict__ core)
{
    __shared__ __align__(16) ull_t Ys[2][GK][66];
    __shared__ __align__(16) ull_t Cs[2][GK][130];

    const int tid = threadIdx.x;
    const int p0 = blockIdx.x * GP;
    const int o0 = blockIdx.y * GO;

    const int yrow = tid >> 2, yq = tid & 3;       // Y loads: 64 rows x 4 chunks
    const int crow = tid >> 1, ch = tid & 1;       // C loads: 128 rows x 2 halves
    const int wid = tid >> 5, lane = tid & 31;
    const int pgrp = (lane & 7) + (wid & 1) * 8;   // 0..15 -> pairs pgrp*4..+3
    const int ogrp = (lane >> 3) + (wid >> 1) * 4; // 0..15 -> o ogrp*8..+7

    // prologue: chunk 0
    {
        const ull_t* yg = &g_Y2[(size_t)(p0 + yrow) * 512 + yq * 4];
        ulonglong2 y0 = *(const ulonglong2*)(yg);
        ulonglong2 y1 = *(const ulonglong2*)(yg + 2);
        Ys[0][yq*4+0][yrow] = y0.x; Ys[0][yq*4+1][yrow] = y0.y;
        Ys[0][yq*4+2][yrow] = y1.x; Ys[0][yq*4+3][yrow] = y1.y;
        const float4* cg = (const float4*)(core + (size_t)(o0 + crow) * 512 + ch * 8);
        float4 c0 = cg[0], c1 = cg[1];
        Cs[0][ch*8+0][crow] = dup_f32x2(c0.x); Cs[0][ch*8+1][crow] = dup_f32x2(c0.y);
        Cs[0][ch*8+2][crow] = dup_f32x2(c0.z); Cs[0][ch*8+3][crow] = dup_f32x2(c0.w);
        Cs[0][ch*8+4][crow] = dup_f32x2(c1.x); Cs[0][ch*8+5][crow] = dup_f32x2(c1.y);
        Cs[0][ch*8+6][crow] = dup_f32x2(c1.z); Cs[0][ch*8+7][crow] = dup_f32x2(c1.w);
    }
    __syncthreads();

    ull_t acc[4][8];
    #pragma unroll
    for (int i = 0; i < 4; i++)
        #pragma unroll
        for (int j = 0; j < 8; j++) acc[i][j] = 0ull;

    for (int kb = 0; kb < 32; kb++) {
        int b = kb & 1;
        ulonglong2 ny0, ny1; float4 nc0, nc1;
        if (kb < 31) {
            const ull_t* yg = &g_Y2[(size_t)(p0 + yrow) * 512 + (kb+1)*GK + yq*4];
            ny0 = *(const ulonglong2*)(yg);
            ny1 = *(const ulonglong2*)(yg + 2);
            const float4* cg = (const float4*)(core + (size_t)(o0 + crow) * 512
                                               + (kb+1)*GK + ch * 8);
            nc0 = cg[0]; nc1 = cg[1];
        }

        #pragma unroll
        for (int hh = 0; hh < GK; hh++) {
            ulonglong2 ya = *(const ulonglong2*)&Ys[b][hh][pgrp*4];
            ulonglong2 yb = *(const ulonglong2*)&Ys[b][hh][pgrp*4 + 2];
            ulonglong2 c0 = *(const ulonglong2*)&Cs[b][hh][ogrp*8];
            ulonglong2 c1 = *(const ulonglong2*)&Cs[b][hh][ogrp*8 + 2];
            ulonglong2 c2 = *(const ulonglong2*)&Cs[b][hh][ogrp*8 + 4];
            ulonglong2 c3 = *(const ulonglong2*)&Cs[b][hh][ogrp*8 + 6];
            ull_t y[4] = {ya.x, ya.y, yb.x, yb.y};
            ull_t c[8] = {c0.x, c0.y, c1.x, c1.y, c2.x, c2.y, c3.x, c3.y};
            #pragma unroll
            for (int i = 0; i < 4; i++)
                #pragma unroll
                for (int j = 0; j < 8; j++)
                    acc[i][j] = fma_f32x2(y[i], c[j], acc[i][j]);
        }

        if (kb < 31) {
            int nb = b ^ 1;
            Ys[nb][yq*4+0][yrow] = ny0.x; Ys[nb][yq*4+1][yrow] = ny0.y;
            Ys[nb][yq*4+2][yrow] = ny1.x; Ys[nb][yq*4+3][yrow] = ny1.y;
            Cs[nb][ch*8+0][crow] = dup_f32x2(nc0.x);
            Cs[nb][ch*8+1][crow] = dup_f32x2(nc0.y);
            Cs[nb][ch*8+2][crow] = dup_f32x2(nc0.z);
            Cs[nb][ch*8+3][crow] = dup_f32x2(nc0.w);
            Cs[nb][ch*8+4][crow] = dup_f32x2(nc1.x);
            Cs[nb][ch*8+5][crow] = dup_f32x2(nc1.y);
            Cs[nb][ch*8+6][crow] = dup_f32x2(nc1.z);
            Cs[nb][ch*8+7][crow] = dup_f32x2(nc1.w);
        }
        __syncthreads();
    }

    #pragma unroll
    for (int i = 0; i < 4; i++) {
        ull_t* zg = &g_Z2[(size_t)(p0 + pgrp*4 + i) * 512 + o0 + ogrp*8];
        ulonglong2 v;
        v.x = acc[i][0]; v.y = acc[i][1]; *(ulonglong2*)(zg)     = v;
        v.x = acc[i][2]; v.y = acc[i][3]; *(ulonglong2*)(zg + 2) = v;
        v.x = acc[i][4]; v.y = acc[i][5]; *(ulonglong2*)(zg + 4) = v;
        v.x = acc[i][6]; v.y = acc[i][7]; *(ulonglong2*)(zg + 6) = v;
    }
}

// ============================================================================
// Kernel 3: output expansion. One CTA = TWO pairs, processed as two passes
// over shared stage buffers; both Z tiles + tables loaded up-front.
// ============================================================================
#define K3_SMEM_ULL (2*512 + 64*17 + 2048 + 16*257 + 3*128)
#define K3_SMEM_BYTES (K3_SMEM_ULL * 8)

__global__ void __launch_bounds__(256) k_output(
    const float* __restrict__ fo0, const float* __restrict__ fo1,
    const float* __restrict__ fo2,
    const float* __restrict__ bias, const float* __restrict__ alpha,
    const float* __restrict__ pds, const int* __restrict__ oinv,
    float* __restrict__ out)
{
    extern __shared__ __align__(16) char smem3[];
    ull_t* Zs   = (ull_t*)smem3;          // [2][512]  [a*64+b*8+c]
    ull_t* e1   = Zs + 1024;              // [64*17]   [(a*8+b)*17 + C]
    ull_t* e2   = e1 + 64*17;             // [2048]    [a*256 + B*16 + C]
    ull_t* arr  = e2 + 2048;              // [16*257]  [A*257 + bc]
    ull_t* fo0t = arr + 16*257;           // [a*16+A]
    ull_t* fo1t = fo0t + 128;             // [b*16+B]
    ull_t* fo2t = fo1t + 128;             // [c*16+C]

    const int tid = threadIdx.x;
    const int pairBase = blockIdx.x * 2;
    const float alphaV = __ldg(alpha);

    // Load BOTH pairs' Z tiles (pair-1 latency hidden behind pass 0).
    const ull_t* zsrc = &g_Z2[(size_t)pairBase * 512];
    #pragma unroll
    for (int k = 0; k < 4; k++) Zs[tid + k*256] = zsrc[tid + k*256];
    if (tid < 128) {
        int M_ = tid >> 3, r_ = tid & 7;      // f[M,r] -> ft[r*16+M]
        fo0t[r_*16 + M_] = dup_f32x2(fo0[tid]);
        fo1t[r_*16 + M_] = dup_f32x2(fo1[tid]);
        fo2t[r_*16 + M_] = dup_f32x2(fo2[tid]);
    }
    __syncthreads();

    for (int pp = 0; pp < 2; pp++) {
        const ull_t* Zp = Zs + pp * 512;

        // Stage 1: contract c. Thread tile 2(ab) x 2(C).
        {
            int ab0 = (tid >> 3) * 2;
            int C0  = (tid & 7) * 2;
            ull_t a00 = 0, a01 = 0, a10 = 0, a11 = 0;
            #pragma unroll
            for (int c_ = 0; c_ < 8; c_++) {
                ull_t z0 = Zp[ab0*8 + c_];
                ull_t z1 = Zp[(ab0+1)*8 + c_];
                ulonglong2 w = *(const ulonglong2*)&fo2t[c_*16 + C0];
                a00 = fma_f32x2(z0, w.x, a00); a01 = fma_f32x2(z0, w.y, a01);
                a10 = fma_f32x2(z1, w.x, a10); a11 = fma_f32x2(z1, w.y, a11);
            }
            e1[ab0*17 + C0]       = a00;
            e1[ab0*17 + C0 + 1]   = a01;
            e1[(ab0+1)*17 + C0]   = a10;
            e1[(ab0+1)*17 + C0+1] = a11;
        }
        __syncthreads();

        // Stage 2: contract b. Thread tile 8(B), fixed (a, C).
        {
            int a_ = tid >> 5;
            int C_ = (tid >> 1) & 15;
            int B0 = (tid & 1) * 8;
            ull_t acc[8];
            #pragma unroll
            for (int j = 0; j < 8; j++) acc[j] = 0ull;
            #pragma unroll
            for (int b_ = 0; b_ < 8; b_++) {
                ull_t ev = e1[(a_*8 + b_)*17 + C_];
                #pragma unroll
                for (int j = 0; j < 4; j++) {
                    ulonglong2 w = *(const ulonglong2*)&fo1t[b_*16 + B0 + 2*j];
                    acc[2*j]   = fma_f32x2(ev, w.x, acc[2*j]);
                    acc[2*j+1] = fma_f32x2(ev, w.y, acc[2*j+1]);
                }
            }
            #pragma unroll
            for (int j = 0; j < 8; j++)
                e2[a_*256 + (B0+j)*16 + C_] = acc[j];
        }
        __syncthreads();

        // Stage 3a: contract a (natural order). Thread tile 2(bc) x 8(A).
        {
            int bc0 = (tid >> 1) * 2;
            int A0  = (tid & 1) * 8;
            ull_t acc[2][8];
            #pragma unroll
            for (int i = 0; i < 2; i++)
                #pragma unroll
                for (int j = 0; j < 8; j++) acc[i][j] = 0ull;
            #pragma unroll
            for (int a_ = 0; a_ < 8; a_++) {
                ull_t z0 = e2[a_*256 + bc0];
                ull_t z1 = e2[a_*256 + bc0 + 1];
                #pragma unroll
                for (int j = 0; j < 4; j++) {
                    ulonglong2 w = *(const ulonglong2*)&fo0t[a_*16 + A0 + 2*j];
                    acc[0][2*j]   = fma_f32x2(z0, w.x, acc[0][2*j]);
                    acc[0][2*j+1] = fma_f32x2(z0, w.y, acc[0][2*j+1]);
                    acc[1][2*j]   = fma_f32x2(z1, w.x, acc[1][2*j]);
                    acc[1][2*j+1] = fma_f32x2(z1, w.y, acc[1][2*j+1]);
                }
            }
            #pragma unroll
            for (int j = 0; j < 8; j++) {
                arr[(A0+j)*257 + bc0]     = acc[0][j];
                arr[(A0+j)*257 + bc0 + 1] = acc[1][j];
            }
        }
        __syncthreads();

        // Stage 3b: permuted read + scale/bias + coalesced store.
        float* o0p = out + (size_t)(pairBase + pp) * 2 * 4096;
        float* o1p = o0p + 4096;
        #pragma unroll
        for (int k = 0; k < 16; k++) {
            int j = tid + k*256;
            int o = __ldg(oinv + j);
            float2 v = unpack_f32x2(arr[o + (o >> 8)]);
            float s = __ldg(pds + j) * alphaV, bb = __ldg(bias + j);
            o0p[j] = v.x * s + bb;
            o1p[j] = v.y * s + bb;
        }
        __syncthreads();   // protect arr/e1 reuse by next pass
    }
}

// ============================================================================
// Launch
// ============================================================================
extern "C" void kernel_launch(void* const* d_in, const int* in_sizes, int n_in,
                              void* d_out, int out_size)
{
    const float* x     = (const float*)d_in[0];
    const float* core  = (const float*)d_in[1];
    const float* fo0   = (const float*)d_in[2];
    const float* fo1   = (const float*)d_in[3];
    const float* fo2   = (const float*)d_in[4];
    const float* fi0   = (const float*)d_in[5];
    const float* fi1   = (const float*)d_in[6];
    const float* fi2   = (const float*)d_in[7];
    const float* bias  = (const float*)d_in[8];
    const float* alpha = (const float*)d_in[9];
    const float* pds   = (const float*)d_in[10];
    const int*   iperm = (const int*)d_in[11];
    const int*   oinv  = (const int*)d_in[12];
    float* out = (float*)d_out;

    int NT = in_sizes[0] / 4096;      // tokens (8192)
    int nPairs = NT / 2;              // 4096

    cudaFuncSetAttribute(k_input, cudaFuncAttributeMaxDynamicSharedMemorySize,
                         K1_SMEM_BYTES);
    cudaFuncSetAttribute(k_output, cudaFuncAttributeMaxDynamicSharedMemorySize,
                         K3_SMEM_BYTES);

    k_input<<<nPairs/2, 256, K1_SMEM_BYTES>>>(x, iperm, fi0, fi1, fi2);
    dim3 ggrid(nPairs / GP, 512 / GO);
    k_gemm<<<ggrid, 256>>>(core);
    k_output<<<nPairs/2, 256, K3_SMEM_BYTES>>>(fo0, fo1, fo2, bias, alpha, pds,
                                               oinv, out);
}